// round 9
// baseline (speedup 1.0000x reference)
#include <cuda_runtime.h>
#include <math.h>

// ---------------------------------------------------------------------------
// Problem constants
// ---------------------------------------------------------------------------
#define B_ 4
#define V_ 8
#define D_ 64
#define N_ 16
#define H_ 32
#define W_ 32
#define HW 1024
#define EPS 1e-5f

// ---------------------------------------------------------------------------
// Scratch (device globals; no dynamic allocation allowed)
// ---------------------------------------------------------------------------
__device__ float  g_du   [B_ * D_ * HW];        // delta * u_t
__device__ float  g_Bv   [B_ * N_ * HW];        // conv_B(u_norm)
__device__ float  g_Cv   [B_ * N_ * HW];        // conv_C(u_norm)
__device__ float  g_A    [D_ * N_];             // -exp(log_A_real)
__device__ float  g_Abar [B_ * D_ * N_ * HW];   // exp(delta * A)  (16.8 MB)
__device__ float2 g_stat [B_ * 4];              // per (b, group): (mu, rsqrt)
__device__ float4 g_wtab [V_ * HW];             // bilinear weights (masked)
__device__ short4 g_itab [V_ * HW];             // padded-smem tap offsets

// ---------------------------------------------------------------------------
// Kernel 0: fused GN-stats (blocks 0..15) + init tables (blocks 16..47)
// Table math is pure fp32: exact for axis rotations (c,s in {0,+-1} lookup),
// continuity of bilinear-with-zero-padding covers the diagonal cases.
// ---------------------------------------------------------------------------
__global__ __launch_bounds__(256)
void k_stats_init(const float* __restrict__ u, const float* __restrict__ log_A_real) {
    int blk = blockIdx.x;
    int tid = threadIdx.x;

    if (blk < 16) {
        const float4* base = (const float4*)(u + ((size_t)blk << 14));
        float s = 0.f, ss = 0.f;
        for (int i = tid; i < 4096; i += 256) {
            float4 v = base[i];
            s += v.x + v.y + v.z + v.w;
            ss = fmaf(v.x, v.x, ss);
            ss = fmaf(v.y, v.y, ss);
            ss = fmaf(v.z, v.z, ss);
            ss = fmaf(v.w, v.w, ss);
        }
        for (int o = 16; o; o >>= 1) {
            s  += __shfl_down_sync(0xffffffffu, s, o);
            ss += __shfl_down_sync(0xffffffffu, ss, o);
        }
        __shared__ float shs[8], shss[8];
        int wid = tid >> 5, lid = tid & 31;
        if (lid == 0) { shs[wid] = s; shss[wid] = ss; }
        __syncthreads();
        if (tid == 0) {
            float S = 0.f, SS = 0.f;
            for (int i = 0; i < 8; i++) { S += shs[i]; SS += shss[i]; }
            float mu  = S / 16384.0f;
            float var = SS / 16384.0f - mu * mu;
            g_stat[blk] = make_float2(mu, rsqrtf(var + EPS));
        }
        return;
    }

    int gid = (blk - 16) * 256 + tid;      // 0..8191 ; one v per block
    if (gid < D_ * N_) {
        g_A[gid] = -expf(log_A_real[gid]);
    }

    {
        int v = gid >> 10;
        int p = gid & 1023;
        int h = p >> 5, w = p & 31;

        float c, sn;
        if ((v & 1) == 0) {
            // exact axis rotations: 0, -90, -180, -270 deg
            int q = v >> 1;
            c  = (q == 0) ? 1.f : (q == 2) ? -1.f : 0.f;
            sn = (q == 1) ? -1.f : (q == 3) ? 1.f : 0.f;
        } else {
            float ang = (float)v * -0.78539816339744830961f;
            c  = cosf(ang);
            sn = sinf(ang);
        }

        float X = ((w + 0.5f) * 2.0f) / 32.0f - 1.0f;   // exact in fp32
        float Y = ((h + 0.5f) * 2.0f) / 32.0f - 1.0f;
        float gx = c * X - sn * Y;
        float gy = sn * X + c * Y;
        float ix = (gx + 1.0f) * 16.0f - 0.5f;
        float iy = (gy + 1.0f) * 16.0f - 0.5f;

        float x0f = floorf(ix), y0f = floorf(iy);
        float wx1 = ix - x0f, wy1 = iy - y0f;
        float wx0 = 1.0f - wx1, wy0 = 1.0f - wy1;
        int x0 = (int)x0f, y0 = (int)y0f;
        int x1 = x0 + 1, y1 = y0 + 1;

        auto ok = [](int yy, int xx) { return yy >= 0 && yy < H_ && xx >= 0 && xx < W_; };
        float w00 = ok(y0, x0) ? wy0 * wx0 : 0.0f;
        float w01 = ok(y0, x1) ? wy0 * wx1 : 0.0f;
        float w10 = ok(y1, x0) ? wy1 * wx0 : 0.0f;
        float w11 = ok(y1, x1) ? wy1 * wx1 : 0.0f;

        auto cl = [](int v_, int hi) { return v_ < 0 ? 0 : (v_ > hi ? hi : v_); };
        int y0c = cl(y0, H_ - 1), y1c = cl(y1, H_ - 1);
        int x0c = cl(x0, W_ - 1), x1c = cl(x1, W_ - 1);
        short i00 = (short)(y0c * 33 + x0c);
        short i01 = (short)(y0c * 33 + x1c);
        short i10 = (short)(y1c * 33 + x0c);
        short i11 = (short)(y1c * 33 + x1c);

        g_wtab[gid] = make_float4(w00, w01, w10, w11);
        g_itab[gid] = make_short4(i00, i01, i10, i11);
    }
}

// ---------------------------------------------------------------------------
// Kernel 1: fused 3x3 convs + inline group-norm, software-pipelined staging.
// Delta blocks (ocq<16) additionally precompute A_bar = exp(delta*A[d,n])
// into g_Abar (shared across all 8 velocity views in k_main).
// ---------------------------------------------------------------------------
__global__ __launch_bounds__(256)
void k_conv(const float* __restrict__ wD, const float* __restrict__ bD,
            const float* __restrict__ wB, const float* __restrict__ wC,
            const float* __restrict__ u_t,
            const float* __restrict__ gw, const float* __restrict__ gb,
            const float* __restrict__ dt_bias_p) {
    int strip = blockIdx.x & 3;
    int rest  = blockIdx.x >> 2;
    int ocq   = rest % 24;
    int b     = rest / 24;
    int tid   = threadIdx.x;

    __shared__ float wsh[4 * D_ * 9];    // 9216 B
    __shared__ float buf[2][2][340];     // 5440 B : [dbuf][ic-in-pair][elem]
    __shared__ float ssc[64], ssh[64];   // per-ic normalize scale/shift
    __shared__ float Ash2[64];           // A[d, n] for the 4 delta channels

    for (int k = tid; k < 4 * D_ * 9; k += 256) {
        int j  = k / (D_ * 9);
        int kk = k - j * (D_ * 9);
        int oc = ocq * 4 + j;
        const float* src;
        if (oc < 64)      src = wD + (size_t)oc * 576;
        else if (oc < 80) src = wB + (size_t)(oc - 64) * 576;
        else              src = wC + (size_t)(oc - 80) * 576;
        wsh[k] = src[kk];
    }
    if (tid < 64) {
        float2 st = g_stat[b * 4 + (tid >> 4)];
        float sc = st.y * gw[tid];
        ssc[tid] = sc;
        ssh[tid] = gb[tid] - st.x * sc;
        if (ocq < 16) Ash2[tid] = g_A[(ocq * 4) * N_ + tid];
    }

    int h0    = strip * 8;
    int local = tid >> 5;    // 0..7
    int col   = tid & 31;

    // hoisted staging index math
    int r1 = tid / 34, c1 = tid - r1 * 34;
    int gr1 = h0 - 1 + r1, gc1 = c1 - 1;
    bool ok1 = (gr1 >= 0) && (gr1 < 32) && (gc1 >= 0) && (gc1 < 32);
    int go1 = ok1 ? gr1 * 32 + gc1 : 0;
    int k2 = tid + 256;
    bool has2 = (k2 < 340);
    int r2 = k2 / 34, c2 = k2 - r2 * 34;
    int gr2 = h0 - 1 + r2, gc2 = c2 - 1;
    bool ok2 = has2 && (gr2 >= 0) && (gr2 < 32) && (gc2 >= 0) && (gc2 < 32);
    int go2 = ok2 ? gr2 * 32 + gc2 : 0;

    const float* ubase = u_t + ((size_t)b << 16);

    float acc[4] = {0.f, 0.f, 0.f, 0.f};

    float ra0 = ok1 ? __ldg(ubase + go1)        : 0.f;
    float ra1 = ok1 ? __ldg(ubase + 1024 + go1) : 0.f;
    float rb0 = ok2 ? __ldg(ubase + go2)        : 0.f;
    float rb1 = ok2 ? __ldg(ubase + 1024 + go2) : 0.f;
    __syncthreads();

    buf[0][0][tid] = ok1 ? fmaf(ra0, ssc[0], ssh[0]) : 0.f;
    buf[0][1][tid] = ok1 ? fmaf(ra1, ssc[1], ssh[1]) : 0.f;
    if (has2) {
        buf[0][0][k2] = ok2 ? fmaf(rb0, ssc[0], ssh[0]) : 0.f;
        buf[0][1][k2] = ok2 ? fmaf(rb1, ssc[1], ssh[1]) : 0.f;
    }
    __syncthreads();

    for (int pair = 0; pair < 32; pair++) {
        int cur = pair & 1;
        int nxt = cur ^ 1;
        int icn0 = pair * 2 + 2;

        if (pair < 31) {
            const float* u0 = ubase + ((size_t)icn0 << 10);
            ra0 = ok1 ? __ldg(u0 + go1)        : 0.f;
            ra1 = ok1 ? __ldg(u0 + 1024 + go1) : 0.f;
            rb0 = ok2 ? __ldg(u0 + go2)        : 0.f;
            rb1 = ok2 ? __ldg(u0 + 1024 + go2) : 0.f;
        }

#pragma unroll
        for (int ii = 0; ii < 2; ii++) {
            int ic = pair * 2 + ii;
            const float* pb = buf[cur][ii];
            const float* wp = &wsh[ic * 9];
#pragma unroll
            for (int r = 0; r < 3; r++) {
#pragma unroll
                for (int c = 0; c < 3; c++) {
                    float t = pb[(local + r) * 34 + col + c];
#pragma unroll
                    for (int j = 0; j < 4; j++)
                        acc[j] = fmaf(t, wp[j * D_ * 9 + r * 3 + c], acc[j]);
                }
            }
        }

        if (pair < 31) {
            buf[nxt][0][tid] = ok1 ? fmaf(ra0, ssc[icn0],     ssh[icn0])     : 0.f;
            buf[nxt][1][tid] = ok1 ? fmaf(ra1, ssc[icn0 + 1], ssh[icn0 + 1]) : 0.f;
            if (has2) {
                buf[nxt][0][k2] = ok2 ? fmaf(rb0, ssc[icn0],     ssh[icn0])     : 0.f;
                buf[nxt][1][k2] = ok2 ? fmaf(rb1, ssc[icn0 + 1], ssh[icn0 + 1]) : 0.f;
            }
        }
        __syncthreads();
    }

    int p = (h0 + local) * 32 + col;
    if (ocq < 16) {
        float dtb = dt_bias_p[0];
#pragma unroll
        for (int j = 0; j < 4; j++) {
            int oc = ocq * 4 + j;
            float x  = acc[j] + bD[oc] + dtb;
            float sp = fmaxf(x, 0.0f) + log1pf(expf(-fabsf(x)));
            float dd = fminf(fmaxf(sp, 1e-4f), 5.0f);
            size_t idx = ((size_t)(b * D_ + oc) << 10) + p;
            g_du[idx] = dd * u_t[idx];
            // A_bar precompute for all n (reused by all 8 velocity views)
            const float* Adp = &Ash2[j * N_];
            size_t abase = ((size_t)(b * D_ + oc) << 14) + p;
#pragma unroll
            for (int n = 0; n < N_; n++)
                g_Abar[abase + ((size_t)n << 10)] = __expf(dd * Adp[n]);
        }
    } else if (ocq < 20) {
#pragma unroll
        for (int j = 0; j < 4; j++) {
            int n = (ocq - 16) * 4 + j;
            g_Bv[((size_t)(b * N_ + n) << 10) + p] = acc[j];
        }
    } else {
#pragma unroll
        for (int j = 0; j < 4; j++) {
            int n = (ocq - 20) * 4 + j;
            g_Cv[((size_t)(b * N_ + n) << 10) + p] = acc[j];
        }
    }
}

// ---------------------------------------------------------------------------
// Kernel 2: main transport + SSM update + einsum (exp-free: loads g_Abar)
// grid = B*V*D = 2048 blocks, 256 threads (4 consecutive pixels/thread)
// ---------------------------------------------------------------------------
__global__ __launch_bounds__(256)
void k_main(const float* __restrict__ s_prev,
            const float* __restrict__ u_t,
            const float* __restrict__ Dp,
            float* __restrict__ y_out,
            float* __restrict__ s_out) {
    int blk = blockIdx.x;                 // = ((b*V + v)*D + d)
    int d = blk & 63;
    int v = (blk >> 6) & 7;
    int b = blk >> 9;

    __shared__ float sp[4 * 1056];        // 16896 B

    int tid = threadIdx.x;
    int p0  = tid * 4;

    size_t bdp = ((size_t)(b * D_ + d) << 10) + p0;
    float4 du4 = *(const float4*)&g_du[bdp];
    float4 u4  = *(const float4*)&u_t[bdp];
    float du[4] = {du4.x, du4.y, du4.z, du4.w};

    const float* sbase  = s_prev + ((size_t)blk << 14);
    float*       snb    = s_out  + ((size_t)blk << 14);
    const float* Bvb    = g_Bv + ((size_t)b << 14) + p0;
    const float* Cvb    = g_Cv + ((size_t)b << 14) + p0;
    const float* Abb    = g_Abar + ((size_t)(b * D_ + d) << 14) + p0;

    float yacc[4] = {0.f, 0.f, 0.f, 0.f};

    if (v == 0 || v == 4) {
        bool mir = (v == 4);
        int fidx = mir ? (255 - tid) : tid;
#pragma unroll
        for (int g = 0; g < 4; g++) {
            float4 sv[4];
#pragma unroll
            for (int j = 0; j < 4; j++)
                sv[j] = __ldcs((const float4*)(sbase + ((size_t)(g * 4 + j) << 10)) + fidx);
#pragma unroll
            for (int j = 0; j < 4; j++) {
                int n = g * 4 + j;
                float4 ab = *(const float4*)&Abb[(size_t)n << 10];
                float4 bv = *(const float4*)&Bvb[(size_t)n << 10];
                float4 cv = *(const float4*)&Cvb[(size_t)n << 10];
                float stv[4];
                if (mir) {
                    stv[0] = sv[j].w; stv[1] = sv[j].z; stv[2] = sv[j].y; stv[3] = sv[j].x;
                } else {
                    stv[0] = sv[j].x; stv[1] = sv[j].y; stv[2] = sv[j].z; stv[3] = sv[j].w;
                }
                float aba[4] = {ab.x, ab.y, ab.z, ab.w};
                float bva[4] = {bv.x, bv.y, bv.z, bv.w};
                float cva[4] = {cv.x, cv.y, cv.z, cv.w};
                float sn[4];
#pragma unroll
                for (int i = 0; i < 4; i++) {
                    sn[i] = fmaf(aba[i], stv[i], du[i] * bva[i]);
                    yacc[i] = fmaf(sn[i], cva[i], yacc[i]);
                }
                float4 so = make_float4(sn[0], sn[1], sn[2], sn[3]);
                __stcs((float4*)&snb[((size_t)n << 10) + p0], so);
            }
        }
    } else {
        float4 wt[4];
        short4 it[4];
        bool   single[4];
#pragma unroll
        for (int i = 0; i < 4; i++) {
            int tabi = (v << 10) + p0 + i;
            wt[i] = g_wtab[tabi];
            it[i] = g_itab[tabi];
            single[i] = (wt[i].y == 0.0f) && (wt[i].z == 0.0f) && (wt[i].w == 0.0f);
        }

        float4 pre[4];
#pragma unroll
        for (int j = 0; j < 4; j++)
            pre[j] = __ldcs((const float4*)sbase + tid + j * 256);

        int soff = (p0 >> 5) * 33 + (p0 & 31);

#pragma unroll
        for (int ph = 0; ph < 4; ph++) {
            __syncthreads();
#pragma unroll
            for (int j = 0; j < 4; j++) {
                float* dst = &sp[j * 1056 + soff];
                dst[0] = pre[j].x; dst[1] = pre[j].y; dst[2] = pre[j].z; dst[3] = pre[j].w;
            }
            __syncthreads();

            if (ph < 3) {
                const float4* src = (const float4*)(sbase + (ph + 1) * 4096);
#pragma unroll
                for (int j = 0; j < 4; j++)
                    pre[j] = __ldcs(src + tid + j * 256);
            }

#pragma unroll
            for (int nn = 0; nn < 4; nn++) {
                int n = ph * 4 + nn;
                const float* pl = &sp[nn * 1056];
                float4 ab = *(const float4*)&Abb[(size_t)n << 10];
                float4 bv = *(const float4*)&Bvb[(size_t)n << 10];
                float4 cv = *(const float4*)&Cvb[(size_t)n << 10];
                float aba[4] = {ab.x, ab.y, ab.z, ab.w};
                float bva[4] = {bv.x, bv.y, bv.z, bv.w};
                float cva[4] = {cv.x, cv.y, cv.z, cv.w};
                float sn[4];
#pragma unroll
                for (int i = 0; i < 4; i++) {
                    float st;
                    if (single[i]) {
                        st = wt[i].x * pl[it[i].x];
                    } else {
                        st = wt[i].x * pl[it[i].x] + wt[i].y * pl[it[i].y]
                           + wt[i].z * pl[it[i].z] + wt[i].w * pl[it[i].w];
                    }
                    sn[i] = fmaf(aba[i], st, du[i] * bva[i]);
                    yacc[i] = fmaf(sn[i], cva[i], yacc[i]);
                }
                float4 so = make_float4(sn[0], sn[1], sn[2], sn[3]);
                __stcs((float4*)&snb[((size_t)n << 10) + p0], so);
            }
        }
    }

    float Dd = __ldg(&Dp[d]);
    float4 yo = make_float4(fmaf(u4.x, Dd, yacc[0]),
                            fmaf(u4.y, Dd, yacc[1]),
                            fmaf(u4.z, Dd, yacc[2]),
                            fmaf(u4.w, Dd, yacc[3]));
    *(float4*)&y_out[((size_t)blk << 10) + p0] = yo;
}

// ---------------------------------------------------------------------------
// Launch
// ---------------------------------------------------------------------------
extern "C" void kernel_launch(void* const* d_in, const int* in_sizes, int n_in,
                              void* d_out, int out_size) {
    const float* u_t      = (const float*)d_in[0];
    const float* s_prev   = (const float*)d_in[1];
    const float* gn_w     = (const float*)d_in[2];
    const float* gn_b     = (const float*)d_in[3];
    const float* cdw      = (const float*)d_in[4];
    const float* cdb      = (const float*)d_in[5];
    const float* cBw      = (const float*)d_in[6];
    const float* cCw      = (const float*)d_in[7];
    const float* logA     = (const float*)d_in[8];
    const float* D_param  = (const float*)d_in[9];
    const float* dt_bias  = (const float*)d_in[10];

    float* y_out = (float*)d_out;                              // (B,V,D,H,W)
    float* s_out = (float*)d_out + (size_t)B_ * V_ * D_ * HW;  // (B,V,D,N,H,W)

    k_stats_init<<<48, 256>>>(u_t, logA);
    k_conv<<<B_ * 24 * 4, 256>>>(cdw, cdb, cBw, cCw, u_t, gn_w, gn_b, dt_bias);
    k_main<<<B_ * V_ * D_, 256>>>(s_prev, u_t, D_param, y_out, s_out);
}

// round 10
// speedup vs baseline: 1.1173x; 1.1173x over previous
#include <cuda_runtime.h>
#include <math.h>

// ---------------------------------------------------------------------------
// Problem constants
// ---------------------------------------------------------------------------
#define B_ 4
#define V_ 8
#define D_ 64
#define N_ 16
#define H_ 32
#define W_ 32
#define HW 1024
#define EPS 1e-5f

// smem plane geometry for the gather: row stride 34 -> bank = (2y+x) % 32,
// conflict-free along the +-45 deg tap diagonals (stride 33 gave (y+x)%32,
// which is CONSTANT along a diagonal -> 32-way conflicts for v=1,5).
#define RSTRIDE 34
#define PLANE   (32 * RSTRIDE)   // 1088 floats

// ---------------------------------------------------------------------------
// Scratch (device globals; no dynamic allocation allowed)
// ---------------------------------------------------------------------------
__device__ float  g_delta[B_ * D_ * HW];   // clipped softplus delta
__device__ float  g_du   [B_ * D_ * HW];   // delta * u_t
__device__ float  g_Bv   [B_ * N_ * HW];   // conv_B(u_norm)
__device__ float  g_Cv   [B_ * N_ * HW];   // conv_C(u_norm)
__device__ float  g_A    [D_ * N_];        // -exp(log_A_real)
__device__ float2 g_stat [B_ * 4];         // per (b, group): (mu, rsqrt)
__device__ float4 g_wtab [V_ * HW];        // bilinear weights (masked)
__device__ short4 g_itab [V_ * HW];        // padded-smem tap offsets (stride 34)

// ---------------------------------------------------------------------------
// Kernel 0: fused GN-stats (blocks 0..15) + init tables (blocks 16..47)
// ---------------------------------------------------------------------------
__global__ __launch_bounds__(256)
void k_stats_init(const float* __restrict__ u, const float* __restrict__ log_A_real) {
    int blk = blockIdx.x;
    int tid = threadIdx.x;

    if (blk < 16) {
        const float4* base = (const float4*)(u + ((size_t)blk << 14));
        float s = 0.f, ss = 0.f;
        for (int i = tid; i < 4096; i += 256) {
            float4 v = base[i];
            s += v.x + v.y + v.z + v.w;
            ss = fmaf(v.x, v.x, ss);
            ss = fmaf(v.y, v.y, ss);
            ss = fmaf(v.z, v.z, ss);
            ss = fmaf(v.w, v.w, ss);
        }
        for (int o = 16; o; o >>= 1) {
            s  += __shfl_down_sync(0xffffffffu, s, o);
            ss += __shfl_down_sync(0xffffffffu, ss, o);
        }
        __shared__ float shs[8], shss[8];
        int wid = tid >> 5, lid = tid & 31;
        if (lid == 0) { shs[wid] = s; shss[wid] = ss; }
        __syncthreads();
        if (tid == 0) {
            float S = 0.f, SS = 0.f;
            for (int i = 0; i < 8; i++) { S += shs[i]; SS += shss[i]; }
            float mu  = S / 16384.0f;
            float var = SS / 16384.0f - mu * mu;
            g_stat[blk] = make_float2(mu, rsqrtf(var + EPS));
        }
        return;
    }

    int gid = (blk - 16) * 256 + tid;      // 0..8191 ; one v per block
    if (gid < D_ * N_) {
        g_A[gid] = -expf(log_A_real[gid]);
    }

    {
        int v = gid >> 10;
        int p = gid & 1023;
        int h = p >> 5, w = p & 31;

        float c, sn;
        if ((v & 1) == 0) {
            // exact axis rotations: 0, -90, -180, -270 deg
            int q = v >> 1;
            c  = (q == 0) ? 1.f : (q == 2) ? -1.f : 0.f;
            sn = (q == 1) ? -1.f : (q == 3) ? 1.f : 0.f;
        } else {
            float ang = (float)v * -0.78539816339744830961f;
            c  = cosf(ang);
            sn = sinf(ang);
        }

        float X = ((w + 0.5f) * 2.0f) / 32.0f - 1.0f;   // exact in fp32
        float Y = ((h + 0.5f) * 2.0f) / 32.0f - 1.0f;
        float gx = c * X - sn * Y;
        float gy = sn * X + c * Y;
        float ix = (gx + 1.0f) * 16.0f - 0.5f;
        float iy = (gy + 1.0f) * 16.0f - 0.5f;

        float x0f = floorf(ix), y0f = floorf(iy);
        float wx1 = ix - x0f, wy1 = iy - y0f;
        float wx0 = 1.0f - wx1, wy0 = 1.0f - wy1;
        int x0 = (int)x0f, y0 = (int)y0f;
        int x1 = x0 + 1, y1 = y0 + 1;

        auto ok = [](int yy, int xx) { return yy >= 0 && yy < H_ && xx >= 0 && xx < W_; };
        float w00 = ok(y0, x0) ? wy0 * wx0 : 0.0f;
        float w01 = ok(y0, x1) ? wy0 * wx1 : 0.0f;
        float w10 = ok(y1, x0) ? wy1 * wx0 : 0.0f;
        float w11 = ok(y1, x1) ? wy1 * wx1 : 0.0f;

        auto cl = [](int v_, int hi) { return v_ < 0 ? 0 : (v_ > hi ? hi : v_); };
        int y0c = cl(y0, H_ - 1), y1c = cl(y1, H_ - 1);
        int x0c = cl(x0, W_ - 1), x1c = cl(x1, W_ - 1);
        short i00 = (short)(y0c * RSTRIDE + x0c);
        short i01 = (short)(y0c * RSTRIDE + x1c);
        short i10 = (short)(y1c * RSTRIDE + x0c);
        short i11 = (short)(y1c * RSTRIDE + x1c);

        g_wtab[gid] = make_float4(w00, w01, w10, w11);
        g_itab[gid] = make_short4(i00, i01, i10, i11);
    }
}

// ---------------------------------------------------------------------------
// Kernel 1: fused 3x3 convs + inline group-norm, software-pipelined staging
// ---------------------------------------------------------------------------
__global__ __launch_bounds__(256)
void k_conv(const float* __restrict__ wD, const float* __restrict__ bD,
            const float* __restrict__ wB, const float* __restrict__ wC,
            const float* __restrict__ u_t,
            const float* __restrict__ gw, const float* __restrict__ gb,
            const float* __restrict__ dt_bias_p) {
    int strip = blockIdx.x & 3;
    int rest  = blockIdx.x >> 2;
    int ocq   = rest % 24;
    int b     = rest / 24;
    int tid   = threadIdx.x;

    __shared__ float wsh[4 * D_ * 9];    // 9216 B
    __shared__ float buf[2][2][340];     // 5440 B : [dbuf][ic-in-pair][elem]
    __shared__ float ssc[64], ssh[64];   // per-ic normalize scale/shift

    for (int k = tid; k < 4 * D_ * 9; k += 256) {
        int j  = k / (D_ * 9);
        int kk = k - j * (D_ * 9);
        int oc = ocq * 4 + j;
        const float* src;
        if (oc < 64)      src = wD + (size_t)oc * 576;
        else if (oc < 80) src = wB + (size_t)(oc - 64) * 576;
        else              src = wC + (size_t)(oc - 80) * 576;
        wsh[k] = src[kk];
    }
    if (tid < 64) {
        float2 st = g_stat[b * 4 + (tid >> 4)];
        float sc = st.y * gw[tid];
        ssc[tid] = sc;
        ssh[tid] = gb[tid] - st.x * sc;
    }

    int h0    = strip * 8;
    int local = tid >> 5;    // 0..7
    int col   = tid & 31;

    // hoisted staging index math
    int r1 = tid / 34, c1 = tid - r1 * 34;
    int gr1 = h0 - 1 + r1, gc1 = c1 - 1;
    bool ok1 = (gr1 >= 0) && (gr1 < 32) && (gc1 >= 0) && (gc1 < 32);
    int go1 = ok1 ? gr1 * 32 + gc1 : 0;
    int k2 = tid + 256;
    bool has2 = (k2 < 340);
    int r2 = k2 / 34, c2 = k2 - r2 * 34;
    int gr2 = h0 - 1 + r2, gc2 = c2 - 1;
    bool ok2 = has2 && (gr2 >= 0) && (gr2 < 32) && (gc2 >= 0) && (gc2 < 32);
    int go2 = ok2 ? gr2 * 32 + gc2 : 0;

    const float* ubase = u_t + ((size_t)b << 16);

    float acc[4] = {0.f, 0.f, 0.f, 0.f};

    float ra0 = ok1 ? __ldg(ubase + go1)        : 0.f;
    float ra1 = ok1 ? __ldg(ubase + 1024 + go1) : 0.f;
    float rb0 = ok2 ? __ldg(ubase + go2)        : 0.f;
    float rb1 = ok2 ? __ldg(ubase + 1024 + go2) : 0.f;
    __syncthreads();

    buf[0][0][tid] = ok1 ? fmaf(ra0, ssc[0], ssh[0]) : 0.f;
    buf[0][1][tid] = ok1 ? fmaf(ra1, ssc[1], ssh[1]) : 0.f;
    if (has2) {
        buf[0][0][k2] = ok2 ? fmaf(rb0, ssc[0], ssh[0]) : 0.f;
        buf[0][1][k2] = ok2 ? fmaf(rb1, ssc[1], ssh[1]) : 0.f;
    }
    __syncthreads();

    for (int pair = 0; pair < 32; pair++) {
        int cur = pair & 1;
        int nxt = cur ^ 1;
        int icn0 = pair * 2 + 2;

        if (pair < 31) {
            const float* u0 = ubase + ((size_t)icn0 << 10);
            ra0 = ok1 ? __ldg(u0 + go1)        : 0.f;
            ra1 = ok1 ? __ldg(u0 + 1024 + go1) : 0.f;
            rb0 = ok2 ? __ldg(u0 + go2)        : 0.f;
            rb1 = ok2 ? __ldg(u0 + 1024 + go2) : 0.f;
        }

#pragma unroll
        for (int ii = 0; ii < 2; ii++) {
            int ic = pair * 2 + ii;
            const float* pb = buf[cur][ii];
            const float* wp = &wsh[ic * 9];
#pragma unroll
            for (int r = 0; r < 3; r++) {
#pragma unroll
                for (int c = 0; c < 3; c++) {
                    float t = pb[(local + r) * 34 + col + c];
#pragma unroll
                    for (int j = 0; j < 4; j++)
                        acc[j] = fmaf(t, wp[j * D_ * 9 + r * 3 + c], acc[j]);
                }
            }
        }

        if (pair < 31) {
            buf[nxt][0][tid] = ok1 ? fmaf(ra0, ssc[icn0],     ssh[icn0])     : 0.f;
            buf[nxt][1][tid] = ok1 ? fmaf(ra1, ssc[icn0 + 1], ssh[icn0 + 1]) : 0.f;
            if (has2) {
                buf[nxt][0][k2] = ok2 ? fmaf(rb0, ssc[icn0],     ssh[icn0])     : 0.f;
                buf[nxt][1][k2] = ok2 ? fmaf(rb1, ssc[icn0 + 1], ssh[icn0 + 1]) : 0.f;
            }
        }
        __syncthreads();
    }

    int p = (h0 + local) * 32 + col;
    if (ocq < 16) {
        float dtb = dt_bias_p[0];
#pragma unroll
        for (int j = 0; j < 4; j++) {
            int oc = ocq * 4 + j;
            float x  = acc[j] + bD[oc] + dtb;
            float sp = fmaxf(x, 0.0f) + log1pf(expf(-fabsf(x)));
            float d  = fminf(fmaxf(sp, 1e-4f), 5.0f);
            size_t idx = ((size_t)(b * D_ + oc) << 10) + p;
            g_delta[idx] = d;
            g_du[idx]    = d * u_t[idx];
        }
    } else if (ocq < 20) {
#pragma unroll
        for (int j = 0; j < 4; j++) {
            int n = (ocq - 16) * 4 + j;
            g_Bv[((size_t)(b * N_ + n) << 10) + p] = acc[j];
        }
    } else {
#pragma unroll
        for (int j = 0; j < 4; j++) {
            int n = (ocq - 20) * 4 + j;
            g_Cv[((size_t)(b * N_ + n) << 10) + p] = acc[j];
        }
    }
}

// ---------------------------------------------------------------------------
// Kernel 2: main transport + SSM update + einsum
// grid = B*V*D = 2048 blocks, 256 threads (4 consecutive pixels/thread)
//   v=0 : identity -> pure streaming, no smem/barriers
//   v=4 : 180 deg -> reversed float4 read, no smem/barriers
//   else: stride-34 padded-smem gather (conflict-free on tap diagonals),
//         register-prefetched 4-plane phases
// ---------------------------------------------------------------------------
__global__ __launch_bounds__(256)
void k_main(const float* __restrict__ s_prev,
            const float* __restrict__ u_t,
            const float* __restrict__ Dp,
            float* __restrict__ y_out,
            float* __restrict__ s_out) {
    int blk = blockIdx.x;                 // = ((b*V + v)*D + d)
    int d = blk & 63;
    int v = (blk >> 6) & 7;
    int b = blk >> 9;

    __shared__ float sp[4 * PLANE];       // 17408 B
    __shared__ float Ash[N_];

    int tid = threadIdx.x;
    int p0  = tid * 4;

    size_t bdp = ((size_t)(b * D_ + d) << 10) + p0;
    float4 dl4 = *(const float4*)&g_delta[bdp];
    float4 du4 = *(const float4*)&g_du[bdp];
    float4 u4  = *(const float4*)&u_t[bdp];
    float dl[4] = {dl4.x, dl4.y, dl4.z, dl4.w};
    float du[4] = {du4.x, du4.y, du4.z, du4.w};

    const float* sbase = s_prev + ((size_t)blk << 14);
    float*       snb   = s_out  + ((size_t)blk << 14);
    const float* Bvb   = g_Bv + ((size_t)b << 14) + p0;
    const float* Cvb   = g_Cv + ((size_t)b << 14) + p0;

    float yacc[4] = {0.f, 0.f, 0.f, 0.f};

    if (v == 0 || v == 4) {
        // exact permutations: identity (v=0) or point reflection (v=4)
        bool mir = (v == 4);
        int fidx = mir ? (255 - tid) : tid;
#pragma unroll
        for (int g = 0; g < 4; g++) {
            float4 sv[4];
#pragma unroll
            for (int j = 0; j < 4; j++)
                sv[j] = __ldcs((const float4*)(sbase + ((size_t)(g * 4 + j) << 10)) + fidx);
#pragma unroll
            for (int j = 0; j < 4; j++) {
                int n = g * 4 + j;
                float A_n = __ldg(&g_A[d * N_ + n]);
                float4 bv = *(const float4*)&Bvb[(size_t)n << 10];
                float4 cv = *(const float4*)&Cvb[(size_t)n << 10];
                float stv[4];
                if (mir) {
                    stv[0] = sv[j].w; stv[1] = sv[j].z; stv[2] = sv[j].y; stv[3] = sv[j].x;
                } else {
                    stv[0] = sv[j].x; stv[1] = sv[j].y; stv[2] = sv[j].z; stv[3] = sv[j].w;
                }
                float bva[4] = {bv.x, bv.y, bv.z, bv.w};
                float cva[4] = {cv.x, cv.y, cv.z, cv.w};
                float sn[4];
#pragma unroll
                for (int i = 0; i < 4; i++) {
                    float ab = __expf(dl[i] * A_n);
                    sn[i] = fmaf(ab, stv[i], du[i] * bva[i]);
                    yacc[i] = fmaf(sn[i], cva[i], yacc[i]);
                }
                float4 so = make_float4(sn[0], sn[1], sn[2], sn[3]);
                __stcs((float4*)&snb[((size_t)n << 10) + p0], so);
            }
        }
    } else {
        if (tid < N_) Ash[tid] = g_A[d * N_ + tid];

        float4 wt[4];
        short4 it[4];
        bool   single[4];
#pragma unroll
        for (int i = 0; i < 4; i++) {
            int tabi = (v << 10) + p0 + i;
            wt[i] = g_wtab[tabi];
            it[i] = g_itab[tabi];
            single[i] = (wt[i].y == 0.0f) && (wt[i].z == 0.0f) && (wt[i].w == 0.0f);
        }

        float4 pre[4];
#pragma unroll
        for (int j = 0; j < 4; j++)
            pre[j] = __ldcs((const float4*)sbase + tid + j * 256);

        int soff = (p0 >> 5) * RSTRIDE + (p0 & 31);

#pragma unroll
        for (int ph = 0; ph < 4; ph++) {
            __syncthreads();             // prev compute done (covers Ash on ph=0)
#pragma unroll
            for (int j = 0; j < 4; j++) {
                float* dst = &sp[j * PLANE + soff];
                dst[0] = pre[j].x; dst[1] = pre[j].y; dst[2] = pre[j].z; dst[3] = pre[j].w;
            }
            __syncthreads();             // staging visible

            if (ph < 3) {
                const float4* src = (const float4*)(sbase + (ph + 1) * 4096);
#pragma unroll
                for (int j = 0; j < 4; j++)
                    pre[j] = __ldcs(src + tid + j * 256);
            }

#pragma unroll
            for (int nn = 0; nn < 4; nn++) {
                int n = ph * 4 + nn;
                const float* pl = &sp[nn * PLANE];
                float A_n = Ash[n];
                float4 bv = *(const float4*)&Bvb[(size_t)n << 10];
                float4 cv = *(const float4*)&Cvb[(size_t)n << 10];
                float bva[4] = {bv.x, bv.y, bv.z, bv.w};
                float cva[4] = {cv.x, cv.y, cv.z, cv.w};
                float sn[4];
#pragma unroll
                for (int i = 0; i < 4; i++) {
                    float st;
                    if (single[i]) {
                        st = wt[i].x * pl[it[i].x];
                    } else {
                        st = wt[i].x * pl[it[i].x] + wt[i].y * pl[it[i].y]
                           + wt[i].z * pl[it[i].z] + wt[i].w * pl[it[i].w];
                    }
                    float ab = __expf(dl[i] * A_n);
                    sn[i] = fmaf(ab, st, du[i] * bva[i]);
                    yacc[i] = fmaf(sn[i], cva[i], yacc[i]);
                }
                float4 so = make_float4(sn[0], sn[1], sn[2], sn[3]);
                __stcs((float4*)&snb[((size_t)n << 10) + p0], so);
            }
        }
    }

    float Dd = __ldg(&Dp[d]);
    float4 yo = make_float4(fmaf(u4.x, Dd, yacc[0]),
                            fmaf(u4.y, Dd, yacc[1]),
                            fmaf(u4.z, Dd, yacc[2]),
                            fmaf(u4.w, Dd, yacc[3]));
    *(float4*)&y_out[((size_t)blk << 10) + p0] = yo;
}

// ---------------------------------------------------------------------------
// Launch
// ---------------------------------------------------------------------------
extern "C" void kernel_launch(void* const* d_in, const int* in_sizes, int n_in,
                              void* d_out, int out_size) {
    const float* u_t      = (const float*)d_in[0];
    const float* s_prev   = (const float*)d_in[1];
    const float* gn_w     = (const float*)d_in[2];
    const float* gn_b     = (const float*)d_in[3];
    const float* cdw      = (const float*)d_in[4];
    const float* cdb      = (const float*)d_in[5];
    const float* cBw      = (const float*)d_in[6];
    const float* cCw      = (const float*)d_in[7];
    const float* logA     = (const float*)d_in[8];
    const float* D_param  = (const float*)d_in[9];
    const float* dt_bias  = (const float*)d_in[10];

    float* y_out = (float*)d_out;                              // (B,V,D,H,W)
    float* s_out = (float*)d_out + (size_t)B_ * V_ * D_ * HW;  // (B,V,D,N,H,W)

    k_stats_init<<<48, 256>>>(u_t, logA);
    k_conv<<<B_ * 24 * 4, 256>>>(cdw, cdb, cBw, cCw, u_t, gn_w, gn_b, dt_bias);
    k_main<<<B_ * V_ * D_, 256>>>(s_prev, u_t, D_param, y_out, s_out);
}

// round 13
// speedup vs baseline: 1.1422x; 1.0223x over previous
#include <cuda_runtime.h>
#include <math.h>

// ---------------------------------------------------------------------------
// Problem constants
// ---------------------------------------------------------------------------
#define B_ 4
#define V_ 8
#define D_ 64
#define N_ 16
#define H_ 32
#define W_ 32
#define HW 1024
#define EPS 1e-5f

// smem plane geometry for the gather: row stride 34 -> bank = (2y+x) % 32,
// conflict-free along the +-45 deg tap diagonals.
#define RSTRIDE 34
#define PLANE   (32 * RSTRIDE)   // 1088 floats

// ---------------------------------------------------------------------------
// Packed f32x2 helpers (FFMA2 path: ptxas never auto-fuses; PTX-only)
// ---------------------------------------------------------------------------
__device__ __forceinline__ unsigned long long pack2(float x, float y) {
    unsigned long long r;
    asm("mov.b64 %0, {%1, %2};" : "=l"(r) : "f"(x), "f"(y));
    return r;
}
__device__ __forceinline__ void unpack2(unsigned long long p, float& x, float& y) {
    asm("mov.b64 {%0, %1}, %2;" : "=f"(x), "=f"(y) : "l"(p));
}
__device__ __forceinline__ void ffma2(unsigned long long& d,
                                      unsigned long long a, unsigned long long b) {
    asm("fma.rn.f32x2 %0, %1, %2, %0;" : "+l"(d) : "l"(a), "l"(b));
}

// ---------------------------------------------------------------------------
// Scratch (device globals; no dynamic allocation allowed)
// ---------------------------------------------------------------------------
__device__ float  g_delta[B_ * D_ * HW];   // clipped softplus delta
__device__ float  g_du   [B_ * D_ * HW];   // delta * u_t
__device__ float  g_Bv   [B_ * N_ * HW];   // conv_B(u_norm)
__device__ float  g_Cv   [B_ * N_ * HW];   // conv_C(u_norm)
__device__ float  g_A    [D_ * N_];        // -exp(log_A_real)
__device__ float2 g_stat [B_ * 4];         // per (b, group): (mu, rsqrt)
__device__ float4 g_wtab [V_ * HW];        // bilinear weights (masked)
__device__ short4 g_itab [V_ * HW];        // padded-smem tap offsets (stride 34)

// ---------------------------------------------------------------------------
// Kernel 0: fused GN-stats (blocks 0..15) + init tables (blocks 16..23)
// 1024 threads/block for 4x the memory-level parallelism of the old version.
// ---------------------------------------------------------------------------
__global__ __launch_bounds__(1024)
void k_stats_init(const float* __restrict__ u, const float* __restrict__ log_A_real) {
    int blk = blockIdx.x;
    int tid = threadIdx.x;

    if (blk < 16) {
        const float4* base = (const float4*)(u + ((size_t)blk << 14));
        float s = 0.f, ss = 0.f;
#pragma unroll
        for (int it = 0; it < 4; it++) {
            float4 v = base[tid + it * 1024];
            s += v.x + v.y + v.z + v.w;
            ss = fmaf(v.x, v.x, ss);
            ss = fmaf(v.y, v.y, ss);
            ss = fmaf(v.z, v.z, ss);
            ss = fmaf(v.w, v.w, ss);
        }
        for (int o = 16; o; o >>= 1) {
            s  += __shfl_down_sync(0xffffffffu, s, o);
            ss += __shfl_down_sync(0xffffffffu, ss, o);
        }
        __shared__ float shs[32], shss[32];
        int wid = tid >> 5, lid = tid & 31;
        if (lid == 0) { shs[wid] = s; shss[wid] = ss; }
        __syncthreads();
        if (tid == 0) {
            float S = 0.f, SS = 0.f;
#pragma unroll
            for (int i = 0; i < 32; i++) { S += shs[i]; SS += shss[i]; }
            float mu  = S / 16384.0f;
            float var = SS / 16384.0f - mu * mu;
            g_stat[blk] = make_float2(mu, rsqrtf(var + EPS));
        }
        return;
    }

    int gid = (blk - 16) * 1024 + tid;      // 0..8191 ; one v per block
    if (gid < D_ * N_) {
        g_A[gid] = -expf(log_A_real[gid]);
    }

    {
        int v = gid >> 10;
        int p = gid & 1023;
        int h = p >> 5, w = p & 31;

        float c, sn;
        if ((v & 1) == 0) {
            // exact axis rotations: 0, -90, -180, -270 deg
            int q = v >> 1;
            c  = (q == 0) ? 1.f : (q == 2) ? -1.f : 0.f;
            sn = (q == 1) ? -1.f : (q == 3) ? 1.f : 0.f;
        } else {
            float ang = (float)v * -0.78539816339744830961f;
            c  = cosf(ang);
            sn = sinf(ang);
        }

        float X = ((w + 0.5f) * 2.0f) / 32.0f - 1.0f;   // exact in fp32
        float Y = ((h + 0.5f) * 2.0f) / 32.0f - 1.0f;
        float gx = c * X - sn * Y;
        float gy = sn * X + c * Y;
        float ix = (gx + 1.0f) * 16.0f - 0.5f;
        float iy = (gy + 1.0f) * 16.0f - 0.5f;

        float x0f = floorf(ix), y0f = floorf(iy);
        float wx1 = ix - x0f, wy1 = iy - y0f;
        float wx0 = 1.0f - wx1, wy0 = 1.0f - wy1;
        int x0 = (int)x0f, y0 = (int)y0f;
        int x1 = x0 + 1, y1 = y0 + 1;

        auto ok = [](int yy, int xx) { return yy >= 0 && yy < H_ && xx >= 0 && xx < W_; };
        float w00 = ok(y0, x0) ? wy0 * wx0 : 0.0f;
        float w01 = ok(y0, x1) ? wy0 * wx1 : 0.0f;
        float w10 = ok(y1, x0) ? wy1 * wx0 : 0.0f;
        float w11 = ok(y1, x1) ? wy1 * wx1 : 0.0f;

        auto cl = [](int v_, int hi) { return v_ < 0 ? 0 : (v_ > hi ? hi : v_); };
        int y0c = cl(y0, H_ - 1), y1c = cl(y1, H_ - 1);
        int x0c = cl(x0, W_ - 1), x1c = cl(x1, W_ - 1);
        short i00 = (short)(y0c * RSTRIDE + x0c);
        short i01 = (short)(y0c * RSTRIDE + x1c);
        short i10 = (short)(y1c * RSTRIDE + x0c);
        short i11 = (short)(y1c * RSTRIDE + x1c);

        g_wtab[gid] = make_float4(w00, w01, w10, w11);
        g_itab[gid] = make_short4(i00, i01, i10, i11);
    }
}

// ---------------------------------------------------------------------------
// Kernel 1: fused 3x3 convs + inline group-norm, software-pipelined staging.
// Weight smem layout [ic][tap][j] -> one LDS.128 per tap serves all 4 ocs;
// accumulation in packed f32x2 (FFMA2) halves the FMA issue count.
// ---------------------------------------------------------------------------
__global__ __launch_bounds__(256)
void k_conv(const float* __restrict__ wD, const float* __restrict__ bD,
            const float* __restrict__ wB, const float* __restrict__ wC,
            const float* __restrict__ u_t,
            const float* __restrict__ gw, const float* __restrict__ gb,
            const float* __restrict__ dt_bias_p) {
    int strip = blockIdx.x & 3;
    int rest  = blockIdx.x >> 2;
    int ocq   = rest % 24;
    int b     = rest / 24;
    int tid   = threadIdx.x;

    __shared__ __align__(16) float wsh[D_ * 9 * 4];  // [ic][tap][j]  9216 B
    __shared__ float buf[2][2][340];                 // 5440 B
    __shared__ float ssc[64], ssh[64];               // per-ic normalize

    // load weights: wsh[ic*36 + tap*4 + j] = W_oc(j)[ic][tap]
    for (int k = tid; k < D_ * 9 * 4; k += 256) {
        int j   = k & 3;
        int tap = (k >> 2) % 9;
        int ic  = k / 36;
        int oc  = ocq * 4 + j;
        const float* src;
        if (oc < 64)      src = wD + (size_t)oc * 576;
        else if (oc < 80) src = wB + (size_t)(oc - 64) * 576;
        else              src = wC + (size_t)(oc - 80) * 576;
        wsh[k] = src[ic * 9 + tap];
    }
    if (tid < 64) {
        float2 st = g_stat[b * 4 + (tid >> 4)];
        float sc = st.y * gw[tid];
        ssc[tid] = sc;
        ssh[tid] = gb[tid] - st.x * sc;
    }

    int h0    = strip * 8;
    int local = tid >> 5;    // 0..7
    int col   = tid & 31;

    // hoisted staging index math
    int r1 = tid / 34, c1 = tid - r1 * 34;
    int gr1 = h0 - 1 + r1, gc1 = c1 - 1;
    bool ok1 = (gr1 >= 0) && (gr1 < 32) && (gc1 >= 0) && (gc1 < 32);
    int go1 = ok1 ? gr1 * 32 + gc1 : 0;
    int k2 = tid + 256;
    bool has2 = (k2 < 340);
    int r2 = k2 / 34, c2 = k2 - r2 * 34;
    int gr2 = h0 - 1 + r2, gc2 = c2 - 1;
    bool ok2 = has2 && (gr2 >= 0) && (gr2 < 32) && (gc2 >= 0) && (gc2 < 32);
    int go2 = ok2 ? gr2 * 32 + gc2 : 0;

    const float* ubase = u_t + ((size_t)b << 16);

    unsigned long long acc01 = 0ULL, acc23 = 0ULL;   // packed (0.f, 0.f)

    float ra0 = ok1 ? __ldg(ubase + go1)        : 0.f;
    float ra1 = ok1 ? __ldg(ubase + 1024 + go1) : 0.f;
    float rb0 = ok2 ? __ldg(ubase + go2)        : 0.f;
    float rb1 = ok2 ? __ldg(ubase + 1024 + go2) : 0.f;
    __syncthreads();

    buf[0][0][tid] = ok1 ? fmaf(ra0, ssc[0], ssh[0]) : 0.f;
    buf[0][1][tid] = ok1 ? fmaf(ra1, ssc[1], ssh[1]) : 0.f;
    if (has2) {
        buf[0][0][k2] = ok2 ? fmaf(rb0, ssc[0], ssh[0]) : 0.f;
        buf[0][1][k2] = ok2 ? fmaf(rb1, ssc[1], ssh[1]) : 0.f;
    }
    __syncthreads();

    for (int pair = 0; pair < 32; pair++) {
        int cur = pair & 1;
        int nxt = cur ^ 1;
        int icn0 = pair * 2 + 2;

        if (pair < 31) {
            const float* u0 = ubase + ((size_t)icn0 << 10);
            ra0 = ok1 ? __ldg(u0 + go1)        : 0.f;
            ra1 = ok1 ? __ldg(u0 + 1024 + go1) : 0.f;
            rb0 = ok2 ? __ldg(u0 + go2)        : 0.f;
            rb1 = ok2 ? __ldg(u0 + 1024 + go2) : 0.f;
        }

#pragma unroll
        for (int ii = 0; ii < 2; ii++) {
            int ic = pair * 2 + ii;
            const float* pb = buf[cur][ii];
            const float* wp = &wsh[ic * 36];
#pragma unroll
            for (int r = 0; r < 3; r++) {
#pragma unroll
                for (int c = 0; c < 3; c++) {
                    float t = pb[(local + r) * 34 + col + c];
                    unsigned long long tt = pack2(t, t);
                    ulonglong2 wv = *(const ulonglong2*)&wp[(r * 3 + c) * 4];
                    ffma2(acc01, tt, wv.x);
                    ffma2(acc23, tt, wv.y);
                }
            }
        }

        if (pair < 31) {
            buf[nxt][0][tid] = ok1 ? fmaf(ra0, ssc[icn0],     ssh[icn0])     : 0.f;
            buf[nxt][1][tid] = ok1 ? fmaf(ra1, ssc[icn0 + 1], ssh[icn0 + 1]) : 0.f;
            if (has2) {
                buf[nxt][0][k2] = ok2 ? fmaf(rb0, ssc[icn0],     ssh[icn0])     : 0.f;
                buf[nxt][1][k2] = ok2 ? fmaf(rb1, ssc[icn0 + 1], ssh[icn0 + 1]) : 0.f;
            }
        }
        __syncthreads();
    }

    float acc[4];
    unpack2(acc01, acc[0], acc[1]);
    unpack2(acc23, acc[2], acc[3]);

    int p = (h0 + local) * 32 + col;
    if (ocq < 16) {
        float dtb = dt_bias_p[0];
#pragma unroll
        for (int j = 0; j < 4; j++) {
            int oc = ocq * 4 + j;
            float x  = acc[j] + bD[oc] + dtb;
            float sp = fmaxf(x, 0.0f) + log1pf(expf(-fabsf(x)));
            float d  = fminf(fmaxf(sp, 1e-4f), 5.0f);
            size_t idx = ((size_t)(b * D_ + oc) << 10) + p;
            g_delta[idx] = d;
            g_du[idx]    = d * u_t[idx];
        }
    } else if (ocq < 20) {
#pragma unroll
        for (int j = 0; j < 4; j++) {
            int n = (ocq - 16) * 4 + j;
            g_Bv[((size_t)(b * N_ + n) << 10) + p] = acc[j];
        }
    } else {
#pragma unroll
        for (int j = 0; j < 4; j++) {
            int n = (ocq - 20) * 4 + j;
            g_Cv[((size_t)(b * N_ + n) << 10) + p] = acc[j];
        }
    }
}

// ---------------------------------------------------------------------------
// Kernel 2: main transport + SSM update + einsum
// grid = B*V*D = 2048 blocks, 256 threads (4 consecutive pixels/thread)
//   v=0 : identity -> pure streaming, no smem/barriers
//   v=4 : 180 deg -> reversed float4 read, no smem/barriers
//   else: DOUBLE-BUFFERED stride-34 padded-smem gather (1 barrier/phase)
// ---------------------------------------------------------------------------
__global__ __launch_bounds__(256)
void k_main(const float* __restrict__ s_prev,
            const float* __restrict__ u_t,
            const float* __restrict__ Dp,
            float* __restrict__ y_out,
            float* __restrict__ s_out) {
    int blk = blockIdx.x;                 // = ((b*V + v)*D + d)
    int d = blk & 63;
    int v = (blk >> 6) & 7;
    int b = blk >> 9;

    __shared__ float sp[2][4 * PLANE];    // 34816 B (double-buffered)
    __shared__ float Ash[N_];

    int tid = threadIdx.x;
    int p0  = tid * 4;

    size_t bdp = ((size_t)(b * D_ + d) << 10) + p0;
    float4 dl4 = *(const float4*)&g_delta[bdp];
    float4 du4 = *(const float4*)&g_du[bdp];
    float4 u4  = *(const float4*)&u_t[bdp];
    float dl[4] = {dl4.x, dl4.y, dl4.z, dl4.w};
    float du[4] = {du4.x, du4.y, du4.z, du4.w};

    const float* sbase = s_prev + ((size_t)blk << 14);
    float*       snb   = s_out  + ((size_t)blk << 14);
    const float* Bvb   = g_Bv + ((size_t)b << 14) + p0;
    const float* Cvb   = g_Cv + ((size_t)b << 14) + p0;

    float yacc[4] = {0.f, 0.f, 0.f, 0.f};

    if (v == 0 || v == 4) {
        // exact permutations: identity (v=0) or point reflection (v=4)
        bool mir = (v == 4);
        int fidx = mir ? (255 - tid) : tid;
#pragma unroll
        for (int g = 0; g < 4; g++) {
            float4 sv[4];
#pragma unroll
            for (int j = 0; j < 4; j++)
                sv[j] = __ldcs((const float4*)(sbase + ((size_t)(g * 4 + j) << 10)) + fidx);
#pragma unroll
            for (int j = 0; j < 4; j++) {
                int n = g * 4 + j;
                float A_n = __ldg(&g_A[d * N_ + n]);
                float4 bv = *(const float4*)&Bvb[(size_t)n << 10];
                float4 cv = *(const float4*)&Cvb[(size_t)n << 10];
                float stv[4];
                if (mir) {
                    stv[0] = sv[j].w; stv[1] = sv[j].z; stv[2] = sv[j].y; stv[3] = sv[j].x;
                } else {
                    stv[0] = sv[j].x; stv[1] = sv[j].y; stv[2] = sv[j].z; stv[3] = sv[j].w;
                }
                float bva[4] = {bv.x, bv.y, bv.z, bv.w};
                float cva[4] = {cv.x, cv.y, cv.z, cv.w};
                float sn[4];
#pragma unroll
                for (int i = 0; i < 4; i++) {
                    float ab = __expf(dl[i] * A_n);
                    sn[i] = fmaf(ab, stv[i], du[i] * bva[i]);
                    yacc[i] = fmaf(sn[i], cva[i], yacc[i]);
                }
                float4 so = make_float4(sn[0], sn[1], sn[2], sn[3]);
                __stcs((float4*)&snb[((size_t)n << 10) + p0], so);
            }
        }
    } else {
        if (tid < N_) Ash[tid] = g_A[d * N_ + tid];

        float4 wt[4];
        short4 it[4];
        bool   single[4];
#pragma unroll
        for (int i = 0; i < 4; i++) {
            int tabi = (v << 10) + p0 + i;
            wt[i] = g_wtab[tabi];
            it[i] = g_itab[tabi];
            single[i] = (wt[i].y == 0.0f) && (wt[i].z == 0.0f) && (wt[i].w == 0.0f);
        }

        int soff = (p0 >> 5) * RSTRIDE + (p0 & 31);

        // prologue: load + stage phase 0 into buffer 0
        float4 pre[4];
#pragma unroll
        for (int j = 0; j < 4; j++)
            pre[j] = __ldcs((const float4*)sbase + tid + j * 256);
#pragma unroll
        for (int j = 0; j < 4; j++) {
            float* dst = &sp[0][j * PLANE + soff];
            dst[0] = pre[j].x; dst[1] = pre[j].y; dst[2] = pre[j].z; dst[3] = pre[j].w;
        }
        __syncthreads();   // buffer 0 + Ash visible

#pragma unroll
        for (int ph = 0; ph < 4; ph++) {
            int cur = ph & 1;

            // prefetch next phase while computing current
            if (ph < 3) {
                const float4* src = (const float4*)(sbase + (ph + 1) * 4096);
#pragma unroll
                for (int j = 0; j < 4; j++)
                    pre[j] = __ldcs(src + tid + j * 256);
            }

#pragma unroll
            for (int nn = 0; nn < 4; nn++) {
                int n = ph * 4 + nn;
                const float* pl = &sp[cur][nn * PLANE];
                float A_n = Ash[n];
                float4 bv = *(const float4*)&Bvb[(size_t)n << 10];
                float4 cv = *(const float4*)&Cvb[(size_t)n << 10];
                float bva[4] = {bv.x, bv.y, bv.z, bv.w};
                float cva[4] = {cv.x, cv.y, cv.z, cv.w};
                float sn[4];
#pragma unroll
                for (int i = 0; i < 4; i++) {
                    float st;
                    if (single[i]) {
                        st = wt[i].x * pl[it[i].x];
                    } else {
                        st = wt[i].x * pl[it[i].x] + wt[i].y * pl[it[i].y]
                           + wt[i].z * pl[it[i].z] + wt[i].w * pl[it[i].w];
                    }
                    float ab = __expf(dl[i] * A_n);
                    sn[i] = fmaf(ab, st, du[i] * bva[i]);
                    yacc[i] = fmaf(sn[i], cva[i], yacc[i]);
                }
                float4 so = make_float4(sn[0], sn[1], sn[2], sn[3]);
                __stcs((float4*)&snb[((size_t)n << 10) + p0], so);
            }

            // stage next phase into the other buffer (safe: that buffer's
            // readers finished before the sync that ended phase ph-1)
            if (ph < 3) {
#pragma unroll
                for (int j = 0; j < 4; j++) {
                    float* dst = &sp[cur ^ 1][j * PLANE + soff];
                    dst[0] = pre[j].x; dst[1] = pre[j].y; dst[2] = pre[j].z; dst[3] = pre[j].w;
                }
                __syncthreads();   // next buffer visible for phase ph+1
            }
        }
    }

    float Dd = __ldg(&Dp[d]);
    float4 yo = make_float4(fmaf(u4.x, Dd, yacc[0]),
                            fmaf(u4.y, Dd, yacc[1]),
                            fmaf(u4.z, Dd, yacc[2]),
                            fmaf(u4.w, Dd, yacc[3]));
    *(float4*)&y_out[((size_t)blk << 10) + p0] = yo;
}

// ---------------------------------------------------------------------------
// Launch
// ---------------------------------------------------------------------------
extern "C" void kernel_launch(void* const* d_in, const int* in_sizes, int n_in,
                              void* d_out, int out_size) {
    const float* u_t      = (const float*)d_in[0];
    const float* s_prev   = (const float*)d_in[1];
    const float* gn_w     = (const float*)d_in[2];
    const float* gn_b     = (const float*)d_in[3];
    const float* cdw      = (const float*)d_in[4];
    const float* cdb      = (const float*)d_in[5];
    const float* cBw      = (const float*)d_in[6];
    const float* cCw      = (const float*)d_in[7];
    const float* logA     = (const float*)d_in[8];
    const float* D_param  = (const float*)d_in[9];
    const float* dt_bias  = (const float*)d_in[10];

    float* y_out = (float*)d_out;                              // (B,V,D,H,W)
    float* s_out = (float*)d_out + (size_t)B_ * V_ * D_ * HW;  // (B,V,D,N,H,W)

    k_stats_init<<<24, 1024>>>(u_t, logA);
    k_conv<<<B_ * 24 * 4, 256>>>(cdw, cdb, cBw, cCw, u_t, gn_w, gn_b, dt_bias);
    k_main<<<B_ * V_ * D_, 256>>>(s_prev, u_t, D_param, y_out, s_out);
}